// round 14
// baseline (speedup 1.0000x reference)
#include <cuda_runtime.h>
#include <cuda_fp16.h>
#include <stdint.h>

#define BB 4
#define NN 2048
#define DD 512
#define HH 8
#define DKK 64

// fp16 scratch written by the projection kernel.
__device__ __align__(16) __half g_hQp[BB * NN * DD];   // [b][n][e]
__device__ __align__(16) __half g_hKp[BB * NN * DD];   // [b][n][e]
__device__ __align__(16) __half g_hVt[BB * DD * NN];   // [b][e][n]  (transposed)
__device__ float g_Zinv[(size_t)BB * NN * NN];         // 64 MB fp32
__device__ __align__(16) __half g_E[(size_t)BB * HH * NN * NN];  // 268 MB
__device__ float g_A[BB * NN * DD];

__device__ __forceinline__ uint32_t f2h2(float lo, float hi) {
    uint32_t r;
    asm("cvt.rn.f16x2.f32 %0, %1, %2;" : "=r"(r) : "f"(hi), "f"(lo));
    return r;
}
__device__ __forceinline__ uint2 f4toh(float4 v) {
    return make_uint2(f2h2(v.x, v.y), f2h2(v.z, v.w));
}
__device__ __forceinline__ void mma16(float c[4], const uint32_t a[4],
                                      const uint32_t b[2]) {
    asm volatile(
        "mma.sync.aligned.m16n8k16.row.col.f32.f16.f16.f32 "
        "{%0,%1,%2,%3},{%4,%5,%6,%7},{%8,%9},{%0,%1,%2,%3};"
        : "+f"(c[0]), "+f"(c[1]), "+f"(c[2]), "+f"(c[3])
        : "r"(a[0]), "r"(a[1]), "r"(a[2]), "r"(a[3]), "r"(b[0]), "r"(b[1]));
}
__device__ __forceinline__ void ldsm4(uint32_t r[4], uint32_t a) {
    asm volatile(
        "ldmatrix.sync.aligned.m8n8.x4.shared.b16 {%0,%1,%2,%3}, [%4];"
        : "=r"(r[0]), "=r"(r[1]), "=r"(r[2]), "=r"(r[3])
        : "r"(a));
}
__device__ __forceinline__ uint32_t smem_u32(const void* p) {
    return (uint32_t)__cvta_generic_to_shared(p);
}
__device__ __forceinline__ void cpa16(uint32_t dst, const void* src) {
    asm volatile("cp.async.ca.shared.global [%0], [%1], 16;" ::"r"(dst),
                 "l"(src));
}
#define CP_COMMIT asm volatile("cp.async.commit_group;" ::: "memory")
#define CP_WAIT1 asm volatile("cp.async.wait_group 1;" ::: "memory")
#define CP_WAIT0 asm volatile("cp.async.wait_group 0;" ::: "memory")

#define LANE_RA(lane) ((((lane) >> 3) & 1) * 8 + ((lane)&7))
#define LANE_HA(lane) (((lane) >> 4) * 8)
#define LANE_RB(lane) ((((lane) >> 4)) * 8 + ((lane)&7))
#define LANE_HB(lane) ((((lane) >> 3) & 1) * 8)

// ---------------------------------------------------------------------------
// 512-K GEMM (fp16 mma): Y[row,e] = sum_d X[row,d]*W[e,d] + bias[e]
// mode 0 (proj): z=0 -> g_hQp, z=1 -> g_hKp, z=2 -> g_hVt (transposed).
// mode 1 (final): fp32 out to Yf.
// ---------------------------------------------------------------------------
#define GSTR 20

__global__ __launch_bounds__(256, 2) void gemm512_kernel(
    const float* __restrict__ X0, const float* __restrict__ X1,
    const float* __restrict__ X2, const float* __restrict__ W,
    const float* __restrict__ bias, float* __restrict__ Yf, int mode) {
    const float* X = (blockIdx.z == 0) ? X0 : (blockIdx.z == 1) ? X1 : X2;

    __shared__ uint32_t sA[128][GSTR];
    __shared__ uint32_t sB[128][GSTR];

    const int tid = threadIdx.x;
    const int lane = tid & 31;
    const int warp = tid >> 5;
    const int wR = warp >> 2;
    const int wC = warp & 3;
    const int row0 = blockIdx.y * 128;
    const int e0 = blockIdx.x * 128;

    const int lr = tid >> 3;
    const int lcf = (tid & 7) * 4;
    const int lcu = (tid & 7) * 2;

    const uint32_t aB = smem_u32(&sA[0][0]);
    const uint32_t bB = smem_u32(&sB[0][0]);
    const int rA = LANE_RA(lane), hA = LANE_HA(lane);
    const int rB = LANE_RB(lane), hB = LANE_HB(lane);

    float acc[4][4][4] = {};
    float4 ra[4], rb[4];

    #pragma unroll
    for (int it = 0; it < 4; it++) {
        int r = lr + it * 32;
        ra[it] = *(const float4*)&X[(size_t)(row0 + r) * DD + lcf];
        rb[it] = *(const float4*)&W[(size_t)(e0 + r) * DD + lcf];
    }

    for (int k0 = 0; k0 < DD; k0 += 32) {
        #pragma unroll
        for (int it = 0; it < 4; it++) {
            int r = lr + it * 32;
            *(uint2*)&sA[r][lcu] = f4toh(ra[it]);
            *(uint2*)&sB[r][lcu] = f4toh(rb[it]);
        }
        __syncthreads();
        if (k0 + 32 < DD) {
            #pragma unroll
            for (int it = 0; it < 4; it++) {
                int r = lr + it * 32;
                ra[it] = *(const float4*)&X[(size_t)(row0 + r) * DD + k0 + 32 + lcf];
                rb[it] = *(const float4*)&W[(size_t)(e0 + r) * DD + k0 + 32 + lcf];
            }
        }
        #pragma unroll
        for (int kk = 0; kk < 32; kk += 16) {
            uint32_t af[4][4], bp[2][4];
            #pragma unroll
            for (int mt = 0; mt < 4; mt++)
                ldsm4(af[mt], aB + (wR * 64 + mt * 16 + rA) * (GSTR * 4) +
                                  (kk + hA) * 2);
            #pragma unroll
            for (int p = 0; p < 2; p++)
                ldsm4(bp[p], bB + (wC * 32 + p * 16 + rB) * (GSTR * 4) +
                                 (kk + hB) * 2);
            #pragma unroll
            for (int mt = 0; mt < 4; mt++)
                #pragma unroll
                for (int nt = 0; nt < 4; nt++)
                    mma16(acc[mt][nt], af[mt], &bp[nt >> 1][(nt & 1) * 2]);
        }
        __syncthreads();
    }

    #pragma unroll
    for (int mt = 0; mt < 4; mt++) {
        int r = row0 + wR * 64 + mt * 16 + (lane >> 2);
        #pragma unroll
        for (int nt = 0; nt < 4; nt++) {
            int c = e0 + wC * 32 + nt * 8 + (lane & 3) * 2;
            float b0 = bias[c], b1 = bias[c + 1];
            float v00 = acc[mt][nt][0] + b0, v01 = acc[mt][nt][1] + b1;
            float v10 = acc[mt][nt][2] + b0, v11 = acc[mt][nt][3] + b1;
            if (mode == 1) {
                *(float2*)&Yf[(size_t)r * DD + c] = make_float2(v00, v01);
                *(float2*)&Yf[(size_t)(r + 8) * DD + c] = make_float2(v10, v11);
            } else if (blockIdx.z < 2) {
                __half* Yh = blockIdx.z ? g_hKp : g_hQp;
                *(uint32_t*)&Yh[(size_t)r * DD + c] = f2h2(v00, v01);
                *(uint32_t*)&Yh[(size_t)(r + 8) * DD + c] = f2h2(v10, v11);
            } else {
                int bb = r >> 11, n = r & (NN - 1);
                size_t base = (size_t)bb * DD * NN;
                g_hVt[base + (size_t)c * NN + n] = __float2half_rn(v00);
                g_hVt[base + (size_t)(c + 1) * NN + n] = __float2half_rn(v01);
                g_hVt[base + (size_t)c * NN + n + 8] = __float2half_rn(v10);
                g_hVt[base + (size_t)(c + 1) * NN + n + 8] = __float2half_rn(v11);
            }
        }
    }
}

// ---------------------------------------------------------------------------
// zinv_kernel: Zinv = 1/sum_h exp(S_h/8)  AND  g_E[b,h] = exp(S_h/8) (fp16).
// Tile 128x128, 512 threads, 16 warps 32x32, cp.async 3-deep.
// ---------------------------------------------------------------------------
#define ZBUF (2 * 128 * GSTR)
#define ZINV_SMEM_BYTES (3 * ZBUF * 4)

__global__ __launch_bounds__(512) void zinv_kernel() {
    extern __shared__ uint32_t zsm[];

    const int tid = threadIdx.x;
    const int lane = tid & 31;
    const int warp = tid >> 5;
    const int wR = warp >> 2;
    const int wC = warp & 3;
    const int b = blockIdx.z;
    const int n0 = blockIdx.y * 128;
    const int m0 = blockIdx.x * 128;
    const __half* Qh = g_hQp + (size_t)b * NN * DD;
    const __half* Kh = g_hKp + (size_t)b * NN * DD;

    const uint32_t base0 = smem_u32(zsm);
    const int rA = LANE_RA(lane), hA = LANE_HA(lane);
    const int rB = LANE_RB(lane), hB = LANE_HB(lane);

    const int crow = tid >> 2;
    const int cseg = tid & 3;

    float z[2][4][4] = {};
    float dot[2][4][4] = {};

    #pragma unroll
    for (int pc = 0; pc < 2; pc++) {
        uint32_t bufB = base0 + pc * (ZBUF * 4);
        cpa16(bufB + (crow * GSTR + cseg * 4) * 4,
              Qh + (size_t)(n0 + crow) * DD + pc * 32 + cseg * 8);
        cpa16(bufB + ((128 + crow) * GSTR + cseg * 4) * 4,
              Kh + (size_t)(m0 + crow) * DD + pc * 32 + cseg * 8);
        CP_COMMIT;
    }

    for (int ch = 0; ch < 16; ch++) {
        if (ch == 15) { CP_WAIT0; } else { CP_WAIT1; }
        __syncthreads();

        const uint32_t qB = base0 + (ch % 3) * (ZBUF * 4);
        const uint32_t kB = qB + 128 * GSTR * 4;

        #pragma unroll
        for (int kk = 0; kk < 32; kk += 16) {
            uint32_t af[2][4], bp[2][4];
            #pragma unroll
            for (int mt = 0; mt < 2; mt++)
                ldsm4(af[mt], qB + (wR * 32 + mt * 16 + rA) * (GSTR * 4) +
                                  (kk + hA) * 2);
            #pragma unroll
            for (int p = 0; p < 2; p++)
                ldsm4(bp[p], kB + (wC * 32 + p * 16 + rB) * (GSTR * 4) +
                                 (kk + hB) * 2);
            #pragma unroll
            for (int mt = 0; mt < 2; mt++)
                #pragma unroll
                for (int nt = 0; nt < 4; nt++)
                    mma16(dot[mt][nt], af[mt], &bp[nt >> 1][(nt & 1) * 2]);
        }

        if (ch & 1) {  // head boundary: fold exp, WRITE E_h, reset dot
            const int h = ch >> 1;
            __half* Eh = g_E + (((size_t)b * HH + h) * NN) * NN;
            #pragma unroll
            for (int mt = 0; mt < 2; mt++) {
                int r = n0 + wR * 32 + mt * 16 + (lane >> 2);
                #pragma unroll
                for (int nt = 0; nt < 4; nt++) {
                    int cc = m0 + wC * 32 + nt * 8 + (lane & 3) * 2;
                    float e0 = __expf(dot[mt][nt][0] * 0.125f);
                    float e1 = __expf(dot[mt][nt][1] * 0.125f);
                    float e2 = __expf(dot[mt][nt][2] * 0.125f);
                    float e3 = __expf(dot[mt][nt][3] * 0.125f);
                    z[mt][nt][0] += e0;
                    z[mt][nt][1] += e1;
                    z[mt][nt][2] += e2;
                    z[mt][nt][3] += e3;
                    *(uint32_t*)&Eh[(size_t)r * NN + cc] = f2h2(e0, e1);
                    *(uint32_t*)&Eh[(size_t)(r + 8) * NN + cc] = f2h2(e2, e3);
                    dot[mt][nt][0] = 0.0f;
                    dot[mt][nt][1] = 0.0f;
                    dot[mt][nt][2] = 0.0f;
                    dot[mt][nt][3] = 0.0f;
                }
            }
        }

        if (ch + 2 < 16) {
            uint32_t bufB = base0 + ((ch + 2) % 3) * (ZBUF * 4);
            int kb = (ch + 2) * 32;
            cpa16(bufB + (crow * GSTR + cseg * 4) * 4,
                  Qh + (size_t)(n0 + crow) * DD + kb + cseg * 8);
            cpa16(bufB + ((128 + crow) * GSTR + cseg * 4) * 4,
                  Kh + (size_t)(m0 + crow) * DD + kb + cseg * 8);
            CP_COMMIT;
        }
    }

    #pragma unroll
    for (int mt = 0; mt < 2; mt++) {
        int r = n0 + wR * 32 + mt * 16 + (lane >> 2);
        #pragma unroll
        for (int nt = 0; nt < 4; nt++) {
            int c = m0 + wC * 32 + nt * 8 + (lane & 3) * 2;
            *(float2*)&g_Zinv[((size_t)b * NN + r) * NN + c] =
                make_float2(1.0f / z[mt][nt][0], 1.0f / z[mt][nt][1]);
            *(float2*)&g_Zinv[((size_t)b * NN + r + 8) * NN + c] =
                make_float2(1.0f / z[mt][nt][2], 1.0f / z[mt][nt][3]);
        }
    }
}

// ---------------------------------------------------------------------------
// attn_kernel (no S recompute): A_h[n,d] = sum_m (E_h[n,m]*Zinv[n,m]) V_h[m,d]
// Per block: (b,h,n-tile 128). 256 threads, 8 warps 4x2 (32x32 warp tiles).
// m-chunks of 64; E/Vt via cp.async 3-deep; Zinv reg-prefetched 1 chunk ahead;
// E normalized IN PLACE (half2 * fp32) then used directly as the mma A tile.
// Smem (u32, stride 36): E bufs 3x(128*36) | V bufs 3x(64*36) = 82944 B.
// ---------------------------------------------------------------------------
#define ASTR 36
#define EBUF_W (128 * ASTR)
#define VBUF_W (64 * ASTR)
#define ATTN_SMEM_BYTES ((3 * EBUF_W + 3 * VBUF_W) * 4)

__global__ __launch_bounds__(256, 2) void attn_kernel() {
    extern __shared__ uint32_t asm_[];

    const int tid = threadIdx.x;
    const int lane = tid & 31;
    const int warp = tid >> 5;
    const int wR = warp >> 1;  // 0..3 (n-band of 32)
    const int wC = warp & 1;   // 0..1 (d-band of 32)
    const int b = blockIdx.z;
    const int h = blockIdx.y;
    const int n0 = blockIdx.x * 128;

    const __half* Eb = g_E + (((size_t)b * HH + h) * NN) * NN;
    const __half* Vth = g_hVt + ((size_t)b * DD + h * DKK) * NN;
    const float* Zb = g_Zinv + (size_t)b * NN * NN;

    const uint32_t smB = smem_u32(asm_);
    const int rA = LANE_RA(lane), hA = LANE_HA(lane);
    const int rB = LANE_RB(lane), hB = LANE_HB(lane);

    const int erow = tid >> 1;          // E cp: 128 rows, 4 segs/thread
    const int eseg0 = (tid & 1) * 4;
    const int vrow = tid >> 2;          // V cp: 64 rows, 2 segs/thread
    const int vseg0 = (tid & 3) * 2;

    const int nrow = tid >> 1;          // normalize: same row split
    const int cu0 = (tid & 1) * 16;     // u32 col base (16 u32 = 32 halves)
    const float* Zrow = Zb + (size_t)(n0 + nrow) * NN + (tid & 1) * 32;

    // Prologue: stage chunks 0,1.
    #pragma unroll
    for (int pc = 0; pc < 2; pc++) {
        uint32_t eBuf = smB + pc * EBUF_W * 4;
        uint32_t vBuf = smB + (3 * EBUF_W + pc * VBUF_W) * 4;
        #pragma unroll
        for (int s = 0; s < 4; s++) {
            int seg = eseg0 + s;
            cpa16(eBuf + (erow * ASTR + seg * 4) * 4,
                  Eb + (size_t)(n0 + erow) * NN + pc * 64 + seg * 8);
        }
        #pragma unroll
        for (int s = 0; s < 2; s++) {
            int seg = vseg0 + s;
            cpa16(vBuf + (vrow * ASTR + seg * 4) * 4,
                  Vth + (size_t)vrow * NN + pc * 64 + seg * 8);
        }
        CP_COMMIT;
    }

    float4 zr[8];
    #pragma unroll
    for (int j = 0; j < 8; j++) zr[j] = *(const float4*)&Zrow[j * 4];

    float accO[2][4][4] = {};

    for (int c = 0; c < NN / 64; c++) {
        const int m0 = c * 64;
        if (c == NN / 64 - 1) { CP_WAIT0; } else { CP_WAIT1; }
        __syncthreads();  // A: E(c)/V(c) landed; PV(c-1) reads done

        // ---- normalize E(c) in place: P = E * Zinv ----
        {
            uint32_t* row = asm_ + (c % 3) * EBUF_W + nrow * ASTR + cu0;
            const float* zf = (const float*)zr;
            #pragma unroll
            for (int s = 0; s < 4; s++) {
                uint4 v = *(uint4*)(row + s * 4);
                uint32_t o[4];
                #pragma unroll
                for (int q = 0; q < 4; q++) {
                    uint32_t hv = (&v.x)[q];
                    __half2 h2 = *reinterpret_cast<__half2*>(&hv);
                    float2 f = __half22float2(h2);
                    o[q] = f2h2(f.x * zf[s * 8 + 2 * q],
                                f.y * zf[s * 8 + 2 * q + 1]);
                }
                *(uint4*)(row + s * 4) = make_uint4(o[0], o[1], o[2], o[3]);
            }
        }
        __syncthreads();  // B: P ready

        // Zinv prefetch for chunk c+1 — hidden behind the PV mma loop.
        if (c + 1 < NN / 64) {
            #pragma unroll
            for (int j = 0; j < 8; j++)
                zr[j] = *(const float4*)&Zrow[(m0 + 64) + j * 4];
        }

        const uint32_t pB = smB + (c % 3) * EBUF_W * 4;
        const uint32_t vB = smB + (3 * EBUF_W + (c % 3) * VBUF_W) * 4;

        // ---- O += P.V (128x64, contract 64) ----
        #pragma unroll
        for (int kk = 0; kk < 64; kk += 16) {
            uint32_t af[2][4], bp[2][4];
            #pragma unroll
            for (int mt = 0; mt < 2; mt++)
                ldsm4(af[mt], pB + (wR * 32 + mt * 16 + rA) * (ASTR * 4) +
                                  (kk + hA) * 2);
            #pragma unroll
            for (int p = 0; p < 2; p++)
                ldsm4(bp[p], vB + (wC * 32 + p * 16 + rB) * (ASTR * 4) +
                                 (kk + hB) * 2);
            #pragma unroll
            for (int mt = 0; mt < 2; mt++)
                #pragma unroll
                for (int nt = 0; nt < 4; nt++)
                    mma16(accO[mt][nt], af[mt], &bp[nt >> 1][(nt & 1) * 2]);
        }

        // Stage chunk c+2 (buffer last read in PV(c-1), two barriers ago).
        if (c + 2 < NN / 64) {
            uint32_t eBuf = smB + ((c + 2) % 3) * EBUF_W * 4;
            uint32_t vBuf = smB + (3 * EBUF_W + ((c + 2) % 3) * VBUF_W) * 4;
            int mb = m0 + 128;
            #pragma unroll
            for (int s = 0; s < 4; s++) {
                int seg = eseg0 + s;
                cpa16(eBuf + (erow * ASTR + seg * 4) * 4,
                      Eb + (size_t)(n0 + erow) * NN + mb + seg * 8);
            }
            #pragma unroll
            for (int s = 0; s < 2; s++) {
                int seg = vseg0 + s;
                cpa16(vBuf + (vrow * ASTR + seg * 4) * 4,
                      Vth + (size_t)vrow * NN + mb + seg * 8);
            }
            CP_COMMIT;
        }
    }

    #pragma unroll
    for (int mt = 0; mt < 2; mt++) {
        int r = n0 + wR * 32 + mt * 16 + (lane >> 2);
        #pragma unroll
        for (int nt = 0; nt < 4; nt++) {
            int cc = h * DKK + wC * 32 + nt * 8 + (lane & 3) * 2;
            *(float2*)&g_A[((size_t)b * NN + r) * DD + cc] =
                make_float2(accO[mt][nt][0], accO[mt][nt][1]);
            *(float2*)&g_A[((size_t)b * NN + r + 8) * DD + cc] =
                make_float2(accO[mt][nt][2], accO[mt][nt][3]);
        }
    }
}

extern "C" void kernel_launch(void* const* d_in, const int* in_sizes, int n_in,
                              void* d_out, int out_size) {
    const float* Q = (const float*)d_in[0];
    const float* K = (const float*)d_in[1];
    const float* V = (const float*)d_in[2];
    const float* Wq = (const float*)d_in[3];
    const float* bq = (const float*)d_in[4];
    const float* Wo = (const float*)d_in[5];
    const float* bo = (const float*)d_in[6];
    float* out = (float*)d_out;

    void* pA = nullptr;
    cudaGetSymbolAddress(&pA, g_A);

    cudaFuncSetAttribute(zinv_kernel, cudaFuncAttributeMaxDynamicSharedMemorySize,
                         ZINV_SMEM_BYTES);
    cudaFuncSetAttribute(attn_kernel, cudaFuncAttributeMaxDynamicSharedMemorySize,
                         ATTN_SMEM_BYTES);

    gemm512_kernel<<<dim3(DD / 128, (BB * NN) / 128, 3), 256>>>(
        Q, K, V, Wq, bq, nullptr, 0);
    zinv_kernel<<<dim3(NN / 128, NN / 128, BB), 512, ZINV_SMEM_BYTES>>>();
    attn_kernel<<<dim3(NN / 128, HH, BB), 256, ATTN_SMEM_BYTES>>>();
    gemm512_kernel<<<dim3(DD / 128, (BB * NN) / 128, 1), 256>>>(
        (const float*)pA, nullptr, nullptr, Wo, bo, out, 1);
}

// round 15
// speedup vs baseline: 1.1644x; 1.1644x over previous
#include <cuda_runtime.h>
#include <cuda_fp16.h>
#include <stdint.h>

#define BB 4
#define NN 2048
#define DD 512
#define HH 8
#define DKK 64

// fp16 scratch written by the projection kernel.
__device__ __align__(16) __half g_hQp[BB * NN * DD];   // [b][n][e]
__device__ __align__(16) __half g_hKp[BB * NN * DD];   // [b][n][e]
__device__ __align__(16) __half g_hVt[BB * DD * NN];   // [b][e][n]  (transposed)
__device__ float g_Zinv[(size_t)BB * NN * NN];         // 64 MB fp32
__device__ float g_A[BB * NN * DD];

__device__ __forceinline__ uint32_t f2h2(float lo, float hi) {
    uint32_t r;
    asm("cvt.rn.f16x2.f32 %0, %1, %2;" : "=r"(r) : "f"(hi), "f"(lo));
    return r;
}
__device__ __forceinline__ uint2 f4toh(float4 v) {
    return make_uint2(f2h2(v.x, v.y), f2h2(v.z, v.w));
}
__device__ __forceinline__ void mma16(float c[4], const uint32_t a[4],
                                      const uint32_t b[2]) {
    asm volatile(
        "mma.sync.aligned.m16n8k16.row.col.f32.f16.f16.f32 "
        "{%0,%1,%2,%3},{%4,%5,%6,%7},{%8,%9},{%0,%1,%2,%3};"
        : "+f"(c[0]), "+f"(c[1]), "+f"(c[2]), "+f"(c[3])
        : "r"(a[0]), "r"(a[1]), "r"(a[2]), "r"(a[3]), "r"(b[0]), "r"(b[1]));
}
__device__ __forceinline__ void ldsm4(uint32_t r[4], uint32_t a) {
    asm volatile(
        "ldmatrix.sync.aligned.m8n8.x4.shared.b16 {%0,%1,%2,%3}, [%4];"
        : "=r"(r[0]), "=r"(r[1]), "=r"(r[2]), "=r"(r[3])
        : "r"(a));
}
__device__ __forceinline__ uint32_t smem_u32(const void* p) {
    return (uint32_t)__cvta_generic_to_shared(p);
}
__device__ __forceinline__ void cpa16(uint32_t dst, const void* src) {
    asm volatile("cp.async.ca.shared.global [%0], [%1], 16;" ::"r"(dst),
                 "l"(src));
}
#define CP_COMMIT asm volatile("cp.async.commit_group;" ::: "memory")
#define CP_WAIT1 asm volatile("cp.async.wait_group 1;" ::: "memory")
#define CP_WAIT0 asm volatile("cp.async.wait_group 0;" ::: "memory")

#define LANE_RA(lane) ((((lane) >> 3) & 1) * 8 + ((lane)&7))
#define LANE_HA(lane) (((lane) >> 4) * 8)
#define LANE_RB(lane) ((((lane) >> 4)) * 8 + ((lane)&7))
#define LANE_HB(lane) ((((lane) >> 3) & 1) * 8)

// ---------------------------------------------------------------------------
// 512-K GEMM (fp16 mma): Y[row,e] = sum_d X[row,d]*W[e,d] + bias[e]
// mode 0 (proj): z=0 -> g_hQp, z=1 -> g_hKp, z=2 -> g_hVt (transposed).
// mode 1 (final): fp32 out to Yf.    (identical to R13)
// ---------------------------------------------------------------------------
#define GSTR 20

__global__ __launch_bounds__(256, 2) void gemm512_kernel(
    const float* __restrict__ X0, const float* __restrict__ X1,
    const float* __restrict__ X2, const float* __restrict__ W,
    const float* __restrict__ bias, float* __restrict__ Yf, int mode) {
    const float* X = (blockIdx.z == 0) ? X0 : (blockIdx.z == 1) ? X1 : X2;

    __shared__ uint32_t sA[128][GSTR];
    __shared__ uint32_t sB[128][GSTR];

    const int tid = threadIdx.x;
    const int lane = tid & 31;
    const int warp = tid >> 5;
    const int wR = warp >> 2;
    const int wC = warp & 3;
    const int row0 = blockIdx.y * 128;
    const int e0 = blockIdx.x * 128;

    const int lr = tid >> 3;
    const int lcf = (tid & 7) * 4;
    const int lcu = (tid & 7) * 2;

    const uint32_t aB = smem_u32(&sA[0][0]);
    const uint32_t bB = smem_u32(&sB[0][0]);
    const int rA = LANE_RA(lane), hA = LANE_HA(lane);
    const int rB = LANE_RB(lane), hB = LANE_HB(lane);

    float acc[4][4][4] = {};
    float4 ra[4], rb[4];

    #pragma unroll
    for (int it = 0; it < 4; it++) {
        int r = lr + it * 32;
        ra[it] = *(const float4*)&X[(size_t)(row0 + r) * DD + lcf];
        rb[it] = *(const float4*)&W[(size_t)(e0 + r) * DD + lcf];
    }

    for (int k0 = 0; k0 < DD; k0 += 32) {
        #pragma unroll
        for (int it = 0; it < 4; it++) {
            int r = lr + it * 32;
            *(uint2*)&sA[r][lcu] = f4toh(ra[it]);
            *(uint2*)&sB[r][lcu] = f4toh(rb[it]);
        }
        __syncthreads();
        if (k0 + 32 < DD) {
            #pragma unroll
            for (int it = 0; it < 4; it++) {
                int r = lr + it * 32;
                ra[it] = *(const float4*)&X[(size_t)(row0 + r) * DD + k0 + 32 + lcf];
                rb[it] = *(const float4*)&W[(size_t)(e0 + r) * DD + k0 + 32 + lcf];
            }
        }
        #pragma unroll
        for (int kk = 0; kk < 32; kk += 16) {
            uint32_t af[4][4], bp[2][4];
            #pragma unroll
            for (int mt = 0; mt < 4; mt++)
                ldsm4(af[mt], aB + (wR * 64 + mt * 16 + rA) * (GSTR * 4) +
                                  (kk + hA) * 2);
            #pragma unroll
            for (int p = 0; p < 2; p++)
                ldsm4(bp[p], bB + (wC * 32 + p * 16 + rB) * (GSTR * 4) +
                                 (kk + hB) * 2);
            #pragma unroll
            for (int mt = 0; mt < 4; mt++)
                #pragma unroll
                for (int nt = 0; nt < 4; nt++)
                    mma16(acc[mt][nt], af[mt], &bp[nt >> 1][(nt & 1) * 2]);
        }
        __syncthreads();
    }

    #pragma unroll
    for (int mt = 0; mt < 4; mt++) {
        int r = row0 + wR * 64 + mt * 16 + (lane >> 2);
        #pragma unroll
        for (int nt = 0; nt < 4; nt++) {
            int c = e0 + wC * 32 + nt * 8 + (lane & 3) * 2;
            float b0 = bias[c], b1 = bias[c + 1];
            float v00 = acc[mt][nt][0] + b0, v01 = acc[mt][nt][1] + b1;
            float v10 = acc[mt][nt][2] + b0, v11 = acc[mt][nt][3] + b1;
            if (mode == 1) {
                *(float2*)&Yf[(size_t)r * DD + c] = make_float2(v00, v01);
                *(float2*)&Yf[(size_t)(r + 8) * DD + c] = make_float2(v10, v11);
            } else if (blockIdx.z < 2) {
                __half* Yh = blockIdx.z ? g_hKp : g_hQp;
                *(uint32_t*)&Yh[(size_t)r * DD + c] = f2h2(v00, v01);
                *(uint32_t*)&Yh[(size_t)(r + 8) * DD + c] = f2h2(v10, v11);
            } else {
                int bb = r >> 11, n = r & (NN - 1);
                size_t base = (size_t)bb * DD * NN;
                g_hVt[base + (size_t)c * NN + n] = __float2half_rn(v00);
                g_hVt[base + (size_t)(c + 1) * NN + n] = __float2half_rn(v01);
                g_hVt[base + (size_t)c * NN + n + 8] = __float2half_rn(v10);
                g_hVt[base + (size_t)(c + 1) * NN + n + 8] = __float2half_rn(v11);
            }
        }
    }
}

// ---------------------------------------------------------------------------
// Zinv[b,n,m] = 1 / sum_h exp( (q_h(n).k_h(m)) / 8 )   (identical to R13)
// Tile 128x128, 512 threads, 16 warps 32x32, cp.async 3-deep, 1 barrier/chunk.
// ---------------------------------------------------------------------------
#define ZBUF (2 * 128 * GSTR)
#define ZINV_SMEM_BYTES (3 * ZBUF * 4)

__global__ __launch_bounds__(512) void zinv_kernel() {
    extern __shared__ uint32_t zsm[];

    const int tid = threadIdx.x;
    const int lane = tid & 31;
    const int warp = tid >> 5;
    const int wR = warp >> 2;
    const int wC = warp & 3;
    const int b = blockIdx.z;
    const int n0 = blockIdx.y * 128;
    const int m0 = blockIdx.x * 128;
    const __half* Qh = g_hQp + (size_t)b * NN * DD;
    const __half* Kh = g_hKp + (size_t)b * NN * DD;

    const uint32_t base0 = smem_u32(zsm);
    const int rA = LANE_RA(lane), hA = LANE_HA(lane);
    const int rB = LANE_RB(lane), hB = LANE_HB(lane);

    const int crow = tid >> 2;
    const int cseg = tid & 3;

    float z[2][4][4] = {};
    float dot[2][4][4] = {};

    #pragma unroll
    for (int pc = 0; pc < 2; pc++) {
        uint32_t bufB = base0 + pc * (ZBUF * 4);
        cpa16(bufB + (crow * GSTR + cseg * 4) * 4,
              Qh + (size_t)(n0 + crow) * DD + pc * 32 + cseg * 8);
        cpa16(bufB + ((128 + crow) * GSTR + cseg * 4) * 4,
              Kh + (size_t)(m0 + crow) * DD + pc * 32 + cseg * 8);
        CP_COMMIT;
    }

    for (int ch = 0; ch < 16; ch++) {
        if (ch == 15) { CP_WAIT0; } else { CP_WAIT1; }
        __syncthreads();

        const uint32_t qB = base0 + (ch % 3) * (ZBUF * 4);
        const uint32_t kB = qB + 128 * GSTR * 4;

        #pragma unroll
        for (int kk = 0; kk < 32; kk += 16) {
            uint32_t af[2][4], bp[2][4];
            #pragma unroll
            for (int mt = 0; mt < 2; mt++)
                ldsm4(af[mt], qB + (wR * 32 + mt * 16 + rA) * (GSTR * 4) +
                                  (kk + hA) * 2);
            #pragma unroll
            for (int p = 0; p < 2; p++)
                ldsm4(bp[p], kB + (wC * 32 + p * 16 + rB) * (GSTR * 4) +
                                 (kk + hB) * 2);
            #pragma unroll
            for (int mt = 0; mt < 2; mt++)
                #pragma unroll
                for (int nt = 0; nt < 4; nt++)
                    mma16(dot[mt][nt], af[mt], &bp[nt >> 1][(nt & 1) * 2]);
        }

        if (ch & 1) {  // head boundary: fold exp
            #pragma unroll
            for (int mt = 0; mt < 2; mt++)
                #pragma unroll
                for (int nt = 0; nt < 4; nt++)
                    #pragma unroll
                    for (int i = 0; i < 4; i++) {
                        z[mt][nt][i] += __expf(dot[mt][nt][i] * 0.125f);
                        dot[mt][nt][i] = 0.0f;
                    }
        }

        if (ch + 2 < 16) {
            uint32_t bufB = base0 + ((ch + 2) % 3) * (ZBUF * 4);
            int kb = (ch + 2) * 32;
            cpa16(bufB + (crow * GSTR + cseg * 4) * 4,
                  Qh + (size_t)(n0 + crow) * DD + kb + cseg * 8);
            cpa16(bufB + ((128 + crow) * GSTR + cseg * 4) * 4,
                  Kh + (size_t)(m0 + crow) * DD + kb + cseg * 8);
            CP_COMMIT;
        }
    }

    #pragma unroll
    for (int mt = 0; mt < 2; mt++) {
        int r = n0 + wR * 32 + mt * 16 + (lane >> 2);
        #pragma unroll
        for (int nt = 0; nt < 4; nt++) {
            int c = m0 + wC * 32 + nt * 8 + (lane & 3) * 2;
            *(float2*)&g_Zinv[((size_t)b * NN + r) * NN + c] =
                make_float2(1.0f / z[mt][nt][0], 1.0f / z[mt][nt][1]);
            *(float2*)&g_Zinv[((size_t)b * NN + r + 8) * NN + c] =
                make_float2(1.0f / z[mt][nt][2], 1.0f / z[mt][nt][3]);
        }
    }
}

// ---------------------------------------------------------------------------
// attn: single-barrier software pipeline. Per block: (b,h,n-tile 128),
// 256 threads, 8 warps 4x2 (32x32 warp tiles), m-chunks of 64.
// Iter c does PV(c) and S(c+1)+epi(c+1) in ONE barrier interval:
//   [wait0: chunk c+1 landed] barrier; stage(c+2); rz(c+1) LDG;
//   PV(c) from sP[c%2]+V(c); S(c+1) from sQ+K(c+1); epi -> sP[(c+1)%2].
// Hazards: sP[(c+1)%2] last read by PV(c-1), one barrier ago. K/V buf
// (c+2)%3 last read in iter c-1 (S(c)/PV(c-1)? -> V(c-1) read iter c-1),
// separated by the barrier. cp(c+2) covered by a full iteration.
// Smem rows (stride 36): sQ[0,128) sP0[128,256) sP1[256,384)
//   K 3x64 [384,576)  V 3x64 [576,768)  = 110592 B -> 2 CTAs/SM.
// ---------------------------------------------------------------------------
#define ASTR 36
#define NCH (NN / 64)
#define ATTN_SMEM_BYTES (768 * ASTR * 4)

__global__ __launch_bounds__(256, 2) void attn_kernel() {
    extern __shared__ uint32_t asm_[];

    const int tid = threadIdx.x;
    const int lane = tid & 31;
    const int warp = tid >> 5;
    const int wR = warp >> 1;  // 0..3 (n-band)
    const int wC = warp & 1;   // 0..1 (m/d-band)
    const int b = blockIdx.z;
    const int h = blockIdx.y;
    const int n0 = blockIdx.x * 128;

    const __half* Qh = g_hQp + (size_t)b * NN * DD + h * DKK;
    const __half* Kh = g_hKp + (size_t)b * NN * DD + h * DKK;
    const __half* Vth = g_hVt + ((size_t)b * DD + h * DKK) * NN;
    const float* Zb = g_Zinv + (size_t)b * NN * NN;

    const uint32_t smB = smem_u32(asm_);
    const uint32_t qB = smB;
    const uint32_t pB0 = smB + 128 * ASTR * 4;
    const uint32_t kB0 = smB + 384 * ASTR * 4;
    const uint32_t vB0 = smB + 576 * ASTR * 4;
    const int rA = LANE_RA(lane), hA = LANE_HA(lane);
    const int rB = LANE_RB(lane), hB = LANE_HB(lane);

    const int qrow = tid >> 1, qs0 = (tid & 1) * 4;
    const int krow = tid >> 2, kseg = tid & 3;
    const int vrow = tid >> 2, vseg0 = (tid & 3) * 2;

    // Stage Q (group 0).
    #pragma unroll
    for (int s = 0; s < 4; s++) {
        int seg = qs0 + s;
        cpa16(qB + (qrow * ASTR + seg * 4) * 4,
              Qh + (size_t)(n0 + qrow) * DD + seg * 8);
    }
    CP_COMMIT;
    // Stage chunks 0,1 (groups 1,2).
    #pragma unroll
    for (int pc = 0; pc < 2; pc++) {
        uint32_t kBuf = kB0 + pc * (64 * ASTR * 4);
        uint32_t vBuf = vB0 + pc * (64 * ASTR * 4);
        #pragma unroll
        for (int s = 0; s < 2; s++) {
            int sk = kseg + s * 4;
            cpa16(kBuf + (krow * ASTR + sk * 4) * 4,
                  Kh + (size_t)(pc * 64 + krow) * DD + sk * 8);
            int sv = vseg0 + s;
            cpa16(vBuf + (vrow * ASTR + sv * 4) * 4,
                  Vth + (size_t)vrow * NN + pc * 64 + sv * 8);
        }
        CP_COMMIT;
    }
    CP_WAIT1;  // Q + chunk0 landed
    __syncthreads();

    const int erl = wR * 32 + (lane >> 2);
    const int ecl = wC * 32 + (lane & 3) * 2;

    // Zinv for chunk 0.
    float2 rz[2][4][2];
    #pragma unroll
    for (int mt = 0; mt < 2; mt++)
        #pragma unroll
        for (int nt = 0; nt < 4; nt++) {
            int rl = erl + mt * 16, cl = ecl + nt * 8;
            rz[mt][nt][0] = *(const float2*)&Zb[(size_t)(n0 + rl) * NN + cl];
            rz[mt][nt][1] = *(const float2*)&Zb[(size_t)(n0 + rl + 8) * NN + cl];
        }

    // Prologue: S(0) + epi -> sP0.
    {
        float accS[2][4][4] = {};
        const uint32_t kB = kB0;
        #pragma unroll
        for (int kk = 0; kk < 64; kk += 16) {
            uint32_t af[2][4], bp[2][4];
            #pragma unroll
            for (int mt = 0; mt < 2; mt++)
                ldsm4(af[mt], qB + (wR * 32 + mt * 16 + rA) * (ASTR * 4) +
                                  (kk + hA) * 2);
            #pragma unroll
            for (int p = 0; p < 2; p++)
                ldsm4(bp[p], kB + (wC * 32 + p * 16 + rB) * (ASTR * 4) +
                                 (kk + hB) * 2);
            #pragma unroll
            for (int mt = 0; mt < 2; mt++)
                #pragma unroll
                for (int nt = 0; nt < 4; nt++)
                    mma16(accS[mt][nt], af[mt], &bp[nt >> 1][(nt & 1) * 2]);
        }
        uint32_t(*sPw)[ASTR] = (uint32_t(*)[ASTR])(asm_ + 128 * ASTR);
        #pragma unroll
        for (int mt = 0; mt < 2; mt++) {
            int rl = erl + mt * 16;
            #pragma unroll
            for (int nt = 0; nt < 4; nt++) {
                int cu = wC * 16 + nt * 4 + (lane & 3);
                sPw[rl][cu] =
                    f2h2(__expf(accS[mt][nt][0] * 0.125f) * rz[mt][nt][0].x,
                         __expf(accS[mt][nt][1] * 0.125f) * rz[mt][nt][0].y);
                sPw[rl + 8][cu] =
                    f2h2(__expf(accS[mt][nt][2] * 0.125f) * rz[mt][nt][1].x,
                         __expf(accS[mt][nt][3] * 0.125f) * rz[mt][nt][1].y);
            }
        }
    }

    float accO[2][4][4] = {};

    for (int c = 0; c < NCH; c++) {
        CP_WAIT0;  // all staged chunks (up to c+1) landed chip-side
        __syncthreads();  // publishes sP[c%2], cp data, frees buf (c+2)%3

        // Stage chunk c+2.
        if (c + 2 < NCH) {
            uint32_t kBuf = kB0 + ((c + 2) % 3) * (64 * ASTR * 4);
            uint32_t vBuf = vB0 + ((c + 2) % 3) * (64 * ASTR * 4);
            int mb = (c + 2) * 64;
            #pragma unroll
            for (int s = 0; s < 2; s++) {
                int sk = kseg + s * 4;
                cpa16(kBuf + (krow * ASTR + sk * 4) * 4,
                      Kh + (size_t)(mb + krow) * DD + sk * 8);
                int sv = vseg0 + s;
                cpa16(vBuf + (vrow * ASTR + sv * 4) * 4,
                      Vth + (size_t)vrow * NN + mb + sv * 8);
            }
            CP_COMMIT;
        }

        // Zinv prefetch for chunk c+1 (consumed in epi below).
        if (c + 1 < NCH) {
            int mb = (c + 1) * 64;
            #pragma unroll
            for (int mt = 0; mt < 2; mt++)
                #pragma unroll
                for (int nt = 0; nt < 4; nt++) {
                    int rl = erl + mt * 16, cl = ecl + nt * 8;
                    rz[mt][nt][0] =
                        *(const float2*)&Zb[(size_t)(n0 + rl) * NN + mb + cl];
                    rz[mt][nt][1] =
                        *(const float2*)&Zb[(size_t)(n0 + rl + 8) * NN + mb + cl];
                }
        }

        // ---- PV(c): O += P.V ----
        {
            const uint32_t pB = pB0 + (c & 1) * (128 * ASTR * 4);
            const uint32_t vB = vB0 + (c % 3) * (64 * ASTR * 4);
            #pragma unroll
            for (int kk = 0; kk < 64; kk += 16) {
                uint32_t af[2][4], bp[2][4];
                #pragma unroll
                for (int mt = 0; mt < 2; mt++)
                    ldsm4(af[mt], pB + (wR * 32 + mt * 16 + rA) * (ASTR * 4) +
                                      (kk + hA) * 2);
                #pragma unroll
                for (int p = 0; p < 2; p++)
                    ldsm4(bp[p], vB + (wC * 32 + p * 16 + rB) * (ASTR * 4) +
                                     (kk + hB) * 2);
                #pragma unroll
                for (int mt = 0; mt < 2; mt++)
                    #pragma unroll
                    for (int nt = 0; nt < 4; nt++)
                        mma16(accO[mt][nt], af[mt], &bp[nt >> 1][(nt & 1) * 2]);
            }
        }

        // ---- S(c+1) + epi -> sP[(c+1)%2] ----
        if (c + 1 < NCH) {
            float accS[2][4][4] = {};
            const uint32_t kB = kB0 + ((c + 1) % 3) * (64 * ASTR * 4);
            #pragma unroll
            for (int kk = 0; kk < 64; kk += 16) {
                uint32_t af[2][4], bp[2][4];
                #pragma unroll
                for (int mt = 0; mt < 2; mt++)
                    ldsm4(af[mt], qB + (wR * 32 + mt * 16 + rA) * (ASTR * 4) +
                                      (kk + hA) * 2);
                #pragma unroll
                for (int p = 0; p < 2; p++)
                    ldsm4(bp[p], kB + (wC * 32 + p * 16 + rB) * (ASTR * 4) +
                                     (kk + hB) * 2);
                #pragma unroll
                for (int mt = 0; mt < 2; mt++)
                    #pragma unroll
                    for (int nt = 0; nt < 4; nt++)
                        mma16(accS[mt][nt], af[mt], &bp[nt >> 1][(nt & 1) * 2]);
            }
            uint32_t(*sPw)[ASTR] =
                (uint32_t(*)[ASTR])(asm_ + (128 + ((c + 1) & 1) * 128) * ASTR);
            #pragma unroll
            for (int mt = 0; mt < 2; mt++) {
                int rl = erl + mt * 16;
                #pragma unroll
                for (int nt = 0; nt < 4; nt++) {
                    int cu = wC * 16 + nt * 4 + (lane & 3);
                    sPw[rl][cu] =
                        f2h2(__expf(accS[mt][nt][0] * 0.125f) * rz[mt][nt][0].x,
                             __expf(accS[mt][nt][1] * 0.125f) * rz[mt][nt][0].y);
                    sPw[rl + 8][cu] =
                        f2h2(__expf(accS[mt][nt][2] * 0.125f) * rz[mt][nt][1].x,
                             __expf(accS[mt][nt][3] * 0.125f) * rz[mt][nt][1].y);
                }
            }
        }
    }

    #pragma unroll
    for (int mt = 0; mt < 2; mt++) {
        int r = n0 + wR * 32 + mt * 16 + (lane >> 2);
        #pragma unroll
        for (int nt = 0; nt < 4; nt++) {
            int cc = h * DKK + wC * 32 + nt * 8 + (lane & 3) * 2;
            *(float2*)&g_A[((size_t)b * NN + r) * DD + cc] =
                make_float2(accO[mt][nt][0], accO[mt][nt][1]);
            *(float2*)&g_A[((size_t)b * NN + r + 8) * DD + cc] =
                make_float2(accO[mt][nt][2], accO[mt][nt][3]);
        }
    }
}

extern "C" void kernel_launch(void* const* d_in, const int* in_sizes, int n_in,
                              void* d_out, int out_size) {
    const float* Q = (const float*)d_in[0];
    const float* K = (const float*)d_in[1];
    const float* V = (const float*)d_in[2];
    const float* Wq = (const float*)d_in[3];
    const float* bq = (const float*)d_in[4];
    const float* Wo = (const float*)d_in[5];
    const float* bo = (const float*)d_in[6];
    float* out = (float*)d_out;

    void* pA = nullptr;
    cudaGetSymbolAddress(&pA, g_A);

    cudaFuncSetAttribute(zinv_kernel, cudaFuncAttributeMaxDynamicSharedMemorySize,
                         ZINV_SMEM_BYTES);
    cudaFuncSetAttribute(attn_kernel, cudaFuncAttributeMaxDynamicSharedMemorySize,
                         ATTN_SMEM_BYTES);

    gemm512_kernel<<<dim3(DD / 128, (BB * NN) / 128, 3), 256>>>(
        Q, K, V, Wq, bq, nullptr, 0);
    zinv_kernel<<<dim3(NN / 128, NN / 128, BB), 512, ZINV_SMEM_BYTES>>>();
    attn_kernel<<<dim3(NN / 128, HH, BB), 256, ATTN_SMEM_BYTES>>>();
    gemm512_kernel<<<dim3(DD / 128, (BB * NN) / 128, 1), 256>>>(
        (const float*)pA, nullptr, nullptr, Wo, bo, out, 1);
}

// round 16
// speedup vs baseline: 1.2178x; 1.0459x over previous
#include <cuda_runtime.h>
#include <cuda_fp16.h>
#include <stdint.h>

#define BB 4
#define NN 2048
#define DD 512
#define HH 8
#define DKK 64

// fp16 scratch written by the projection kernel.
__device__ __align__(16) __half g_hQp[BB * NN * DD];   // [b][n][e]
__device__ __align__(16) __half g_hKp[BB * NN * DD];   // [b][n][e]
__device__ __align__(16) __half g_hVt[BB * DD * NN];   // [b][e][n]  (transposed)
__device__ float g_Zinv[(size_t)BB * NN * NN];         // 64 MB fp32
__device__ float g_A[BB * NN * DD];

__device__ __forceinline__ uint32_t f2h2(float lo, float hi) {
    uint32_t r;
    asm("cvt.rn.f16x2.f32 %0, %1, %2;" : "=r"(r) : "f"(hi), "f"(lo));
    return r;
}
__device__ __forceinline__ uint2 f4toh(float4 v) {
    return make_uint2(f2h2(v.x, v.y), f2h2(v.z, v.w));
}
__device__ __forceinline__ void mma16(float c[4], const uint32_t a[4],
                                      const uint32_t b[2]) {
    asm volatile(
        "mma.sync.aligned.m16n8k16.row.col.f32.f16.f16.f32 "
        "{%0,%1,%2,%3},{%4,%5,%6,%7},{%8,%9},{%0,%1,%2,%3};"
        : "+f"(c[0]), "+f"(c[1]), "+f"(c[2]), "+f"(c[3])
        : "r"(a[0]), "r"(a[1]), "r"(a[2]), "r"(a[3]), "r"(b[0]), "r"(b[1]));
}
__device__ __forceinline__ void ldsm4(uint32_t r[4], uint32_t a) {
    asm volatile(
        "ldmatrix.sync.aligned.m8n8.x4.shared.b16 {%0,%1,%2,%3}, [%4];"
        : "=r"(r[0]), "=r"(r[1]), "=r"(r[2]), "=r"(r[3])
        : "r"(a));
}
__device__ __forceinline__ uint32_t smem_u32(const void* p) {
    return (uint32_t)__cvta_generic_to_shared(p);
}
__device__ __forceinline__ void cpa16(uint32_t dst, const void* src) {
    asm volatile("cp.async.ca.shared.global [%0], [%1], 16;" ::"r"(dst),
                 "l"(src));
}
#define CP_COMMIT asm volatile("cp.async.commit_group;" ::: "memory")
#define CP_WAIT1 asm volatile("cp.async.wait_group 1;" ::: "memory")
#define CP_WAIT0 asm volatile("cp.async.wait_group 0;" ::: "memory")

#define LANE_RA(lane) ((((lane) >> 3) & 1) * 8 + ((lane)&7))
#define LANE_HA(lane) (((lane) >> 4) * 8)
#define LANE_RB(lane) ((((lane) >> 4)) * 8 + ((lane)&7))
#define LANE_HB(lane) ((((lane) >> 3) & 1) * 8)

// ---------------------------------------------------------------------------
// 512-K GEMM (fp16 mma): Y[row,e] = sum_d X[row,d]*W[e,d] + bias[e]
// z = blockIdx.z + zbase: 0 -> g_hQp, 1 -> g_hKp, 2 -> g_hVt (transposed).
// mode 1: fp32 out to Yf (z must be 0).
// ---------------------------------------------------------------------------
#define GSTR 20

__global__ __launch_bounds__(256, 2) void gemm512_kernel(
    const float* __restrict__ X0, const float* __restrict__ X1,
    const float* __restrict__ X2, const float* __restrict__ W,
    const float* __restrict__ bias, float* __restrict__ Yf, int mode,
    int zbase) {
    const int z = blockIdx.z + zbase;
    const float* X = (z == 0) ? X0 : (z == 1) ? X1 : X2;

    __shared__ uint32_t sA[128][GSTR];
    __shared__ uint32_t sB[128][GSTR];

    const int tid = threadIdx.x;
    const int lane = tid & 31;
    const int warp = tid >> 5;
    const int wR = warp >> 2;
    const int wC = warp & 3;
    const int row0 = blockIdx.y * 128;
    const int e0 = blockIdx.x * 128;

    const int lr = tid >> 3;
    const int lcf = (tid & 7) * 4;
    const int lcu = (tid & 7) * 2;

    const uint32_t aB = smem_u32(&sA[0][0]);
    const uint32_t bB = smem_u32(&sB[0][0]);
    const int rA = LANE_RA(lane), hA = LANE_HA(lane);
    const int rB = LANE_RB(lane), hB = LANE_HB(lane);

    float acc[4][4][4] = {};
    float4 ra[4], rb[4];

    #pragma unroll
    for (int it = 0; it < 4; it++) {
        int r = lr + it * 32;
        ra[it] = *(const float4*)&X[(size_t)(row0 + r) * DD + lcf];
        rb[it] = *(const float4*)&W[(size_t)(e0 + r) * DD + lcf];
    }

    for (int k0 = 0; k0 < DD; k0 += 32) {
        #pragma unroll
        for (int it = 0; it < 4; it++) {
            int r = lr + it * 32;
            *(uint2*)&sA[r][lcu] = f4toh(ra[it]);
            *(uint2*)&sB[r][lcu] = f4toh(rb[it]);
        }
        __syncthreads();
        if (k0 + 32 < DD) {
            #pragma unroll
            for (int it = 0; it < 4; it++) {
                int r = lr + it * 32;
                ra[it] = *(const float4*)&X[(size_t)(row0 + r) * DD + k0 + 32 + lcf];
                rb[it] = *(const float4*)&W[(size_t)(e0 + r) * DD + k0 + 32 + lcf];
            }
        }
        #pragma unroll
        for (int kk = 0; kk < 32; kk += 16) {
            uint32_t af[4][4], bp[2][4];
            #pragma unroll
            for (int mt = 0; mt < 4; mt++)
                ldsm4(af[mt], aB + (wR * 64 + mt * 16 + rA) * (GSTR * 4) +
                                  (kk + hA) * 2);
            #pragma unroll
            for (int p = 0; p < 2; p++)
                ldsm4(bp[p], bB + (wC * 32 + p * 16 + rB) * (GSTR * 4) +
                                 (kk + hB) * 2);
            #pragma unroll
            for (int mt = 0; mt < 4; mt++)
                #pragma unroll
                for (int nt = 0; nt < 4; nt++)
                    mma16(acc[mt][nt], af[mt], &bp[nt >> 1][(nt & 1) * 2]);
        }
        __syncthreads();
    }

    #pragma unroll
    for (int mt = 0; mt < 4; mt++) {
        int r = row0 + wR * 64 + mt * 16 + (lane >> 2);
        #pragma unroll
        for (int nt = 0; nt < 4; nt++) {
            int c = e0 + wC * 32 + nt * 8 + (lane & 3) * 2;
            float b0 = bias[c], b1 = bias[c + 1];
            float v00 = acc[mt][nt][0] + b0, v01 = acc[mt][nt][1] + b1;
            float v10 = acc[mt][nt][2] + b0, v11 = acc[mt][nt][3] + b1;
            if (mode == 1) {
                *(float2*)&Yf[(size_t)r * DD + c] = make_float2(v00, v01);
                *(float2*)&Yf[(size_t)(r + 8) * DD + c] = make_float2(v10, v11);
            } else if (z < 2) {
                __half* Yh = z ? g_hKp : g_hQp;
                *(uint32_t*)&Yh[(size_t)r * DD + c] = f2h2(v00, v01);
                *(uint32_t*)&Yh[(size_t)(r + 8) * DD + c] = f2h2(v10, v11);
            } else {
                int bb = r >> 11, n = r & (NN - 1);
                size_t base = (size_t)bb * DD * NN;
                g_hVt[base + (size_t)c * NN + n] = __float2half_rn(v00);
                g_hVt[base + (size_t)(c + 1) * NN + n] = __float2half_rn(v01);
                g_hVt[base + (size_t)c * NN + n + 8] = __float2half_rn(v10);
                g_hVt[base + (size_t)(c + 1) * NN + n + 8] = __float2half_rn(v11);
            }
        }
    }
}

// ---------------------------------------------------------------------------
// Zinv[b,n,m] = 1 / sum_h exp( (q_h(n).k_h(m)) / 8 )   (R13 version, proven)
// Tile 128x128, 512 threads, 16 warps 32x32, cp.async 3-deep, 1 barrier/chunk.
// ---------------------------------------------------------------------------
#define ZBUF (2 * 128 * GSTR)
#define ZINV_SMEM_BYTES (3 * ZBUF * 4)

__global__ __launch_bounds__(512) void zinv_kernel() {
    extern __shared__ uint32_t zsm[];

    const int tid = threadIdx.x;
    const int lane = tid & 31;
    const int warp = tid >> 5;
    const int wR = warp >> 2;
    const int wC = warp & 3;
    const int b = blockIdx.z;
    const int n0 = blockIdx.y * 128;
    const int m0 = blockIdx.x * 128;
    const __half* Qh = g_hQp + (size_t)b * NN * DD;
    const __half* Kh = g_hKp + (size_t)b * NN * DD;

    const uint32_t base0 = smem_u32(zsm);
    const int rA = LANE_RA(lane), hA = LANE_HA(lane);
    const int rB = LANE_RB(lane), hB = LANE_HB(lane);

    const int crow = tid >> 2;
    const int cseg = tid & 3;

    float z[2][4][4] = {};
    float dot[2][4][4] = {};

    #pragma unroll
    for (int pc = 0; pc < 2; pc++) {
        uint32_t bufB = base0 + pc * (ZBUF * 4);
        cpa16(bufB + (crow * GSTR + cseg * 4) * 4,
              Qh + (size_t)(n0 + crow) * DD + pc * 32 + cseg * 8);
        cpa16(bufB + ((128 + crow) * GSTR + cseg * 4) * 4,
              Kh + (size_t)(m0 + crow) * DD + pc * 32 + cseg * 8);
        CP_COMMIT;
    }

    for (int ch = 0; ch < 16; ch++) {
        if (ch == 15) { CP_WAIT0; } else { CP_WAIT1; }
        __syncthreads();

        const uint32_t qB = base0 + (ch % 3) * (ZBUF * 4);
        const uint32_t kB = qB + 128 * GSTR * 4;

        #pragma unroll
        for (int kk = 0; kk < 32; kk += 16) {
            uint32_t af[2][4], bp[2][4];
            #pragma unroll
            for (int mt = 0; mt < 2; mt++)
                ldsm4(af[mt], qB + (wR * 32 + mt * 16 + rA) * (GSTR * 4) +
                                  (kk + hA) * 2);
            #pragma unroll
            for (int p = 0; p < 2; p++)
                ldsm4(bp[p], kB + (wC * 32 + p * 16 + rB) * (GSTR * 4) +
                                 (kk + hB) * 2);
            #pragma unroll
            for (int mt = 0; mt < 2; mt++)
                #pragma unroll
                for (int nt = 0; nt < 4; nt++)
                    mma16(dot[mt][nt], af[mt], &bp[nt >> 1][(nt & 1) * 2]);
        }

        if (ch & 1) {  // head boundary: fold exp
            #pragma unroll
            for (int mt = 0; mt < 2; mt++)
                #pragma unroll
                for (int nt = 0; nt < 4; nt++)
                    #pragma unroll
                    for (int i = 0; i < 4; i++) {
                        z[mt][nt][i] += __expf(dot[mt][nt][i] * 0.125f);
                        dot[mt][nt][i] = 0.0f;
                    }
        }

        if (ch + 2 < 16) {
            uint32_t bufB = base0 + ((ch + 2) % 3) * (ZBUF * 4);
            int kb = (ch + 2) * 32;
            cpa16(bufB + (crow * GSTR + cseg * 4) * 4,
                  Qh + (size_t)(n0 + crow) * DD + kb + cseg * 8);
            cpa16(bufB + ((128 + crow) * GSTR + cseg * 4) * 4,
                  Kh + (size_t)(m0 + crow) * DD + kb + cseg * 8);
            CP_COMMIT;
        }
    }

    #pragma unroll
    for (int mt = 0; mt < 2; mt++) {
        int r = n0 + wR * 32 + mt * 16 + (lane >> 2);
        #pragma unroll
        for (int nt = 0; nt < 4; nt++) {
            int c = m0 + wC * 32 + nt * 8 + (lane & 3) * 2;
            *(float2*)&g_Zinv[((size_t)b * NN + r) * NN + c] =
                make_float2(1.0f / z[mt][nt][0], 1.0f / z[mt][nt][1]);
            *(float2*)&g_Zinv[((size_t)b * NN + r + 8) * NN + c] =
                make_float2(1.0f / z[mt][nt][2], 1.0f / z[mt][nt][3]);
        }
    }
}

// ---------------------------------------------------------------------------
// attn (R13 two-barrier schedule, proven 403.8): per block (b, h, n-tile 128).
// GRID SWIZZLE: h = blockIdx.x (fastest) so the 8 head-blocks sharing the
// same Zinv rows are schedule-adjacent (L2 temporal locality).
// 256 threads, 8 warps 4x2 (32x32 warp tiles), m-chunks of 64,
// Q/K/V via cp.async (K/V 3-deep), Zinv reg-prefetched behind S phase.
// ---------------------------------------------------------------------------
#define ASTR 36
#define ATTN_SMEM_BYTES (640 * ASTR * 4)

__global__ __launch_bounds__(256, 2) void attn_kernel() {
    extern __shared__ uint32_t asm_[];

    const int tid = threadIdx.x;
    const int lane = tid & 31;
    const int warp = tid >> 5;
    const int wR = warp >> 1;  // 0..3
    const int wC = warp & 1;   // 0..1
    const int b = blockIdx.z;
    const int h = blockIdx.x;              // h fastest
    const int n0 = blockIdx.y * 128;

    const __half* Qh = g_hQp + (size_t)b * NN * DD + h * DKK;
    const __half* Kh = g_hKp + (size_t)b * NN * DD + h * DKK;
    const __half* Vth = g_hVt + ((size_t)b * DD + h * DKK) * NN;
    const float* Zb = g_Zinv + (size_t)b * NN * NN;

    const uint32_t smB = smem_u32(asm_);
    const uint32_t qB = smB;
    const uint32_t pB = smB + 128 * ASTR * 4;
    const uint32_t kB0 = smB + 256 * ASTR * 4;
    const uint32_t vB0 = smB + 448 * ASTR * 4;
    const int rA = LANE_RA(lane), hA = LANE_HA(lane);
    const int rB = LANE_RB(lane), hB = LANE_HB(lane);

    // Q prologue: 128 rows x 8 segs of 16B; 4 per thread.
    {
        int qrow = tid >> 1;
        int sbase = (tid & 1) * 4;
        #pragma unroll
        for (int s = 0; s < 4; s++) {
            int seg = sbase + s;
            cpa16(qB + (qrow * ASTR + seg * 4) * 4,
                  Qh + (size_t)(n0 + qrow) * DD + seg * 8);
        }
        CP_COMMIT;
    }

    const int krow = tid >> 2;
    const int kseg = tid & 3;

    // Prologue: chunks 0,1.
    #pragma unroll
    for (int pc = 0; pc < 2; pc++) {
        uint32_t kBuf = kB0 + pc * (64 * ASTR * 4);
        uint32_t vBuf = vB0 + pc * (64 * ASTR * 4);
        #pragma unroll
        for (int s = 0; s < 2; s++) {
            int seg = kseg + s * 4;
            cpa16(kBuf + (krow * ASTR + seg * 4) * 4,
                  Kh + (size_t)(pc * 64 + krow) * DD + seg * 8);
            cpa16(vBuf + (krow * ASTR + seg * 4) * 4,
                  Vth + (size_t)krow * NN + pc * 64 + seg * 8);
        }
        CP_COMMIT;
    }

    const int erl = wR * 32 + (lane >> 2);
    const int ecl = wC * 32 + (lane & 3) * 2;

    float accO[2][4][4] = {};

    for (int c = 0; c < NN / 64; c++) {
        const int m0 = c * 64;

        // Zinv(c) register prefetch — hidden behind the S phase.
        float2 rz[2][4][2];
        #pragma unroll
        for (int mt = 0; mt < 2; mt++)
            #pragma unroll
            for (int nt = 0; nt < 4; nt++) {
                int rl = erl + mt * 16, cl = ecl + nt * 8;
                rz[mt][nt][0] =
                    *(const float2*)&Zb[(size_t)(n0 + rl) * NN + m0 + cl];
                rz[mt][nt][1] =
                    *(const float2*)&Zb[(size_t)(n0 + rl + 8) * NN + m0 + cl];
            }

        if (c == NN / 64 - 1) { CP_WAIT0; } else { CP_WAIT1; }
        __syncthreads();  // A: K/V(c) ready; PV(c-1) sP reads done

        const uint32_t kB = kB0 + (c % 3) * (64 * ASTR * 4);
        const uint32_t vB = vB0 + (c % 3) * (64 * ASTR * 4);

        // ---- S = Q.K^T (128x64, contract 64) ----
        float accS[2][4][4] = {};
        #pragma unroll
        for (int kk = 0; kk < 64; kk += 16) {
            uint32_t af[2][4], bp[2][4];
            #pragma unroll
            for (int mt = 0; mt < 2; mt++)
                ldsm4(af[mt], qB + (wR * 32 + mt * 16 + rA) * (ASTR * 4) +
                                  (kk + hA) * 2);
            #pragma unroll
            for (int p = 0; p < 2; p++)
                ldsm4(bp[p], kB + (wC * 32 + p * 16 + rB) * (ASTR * 4) +
                                 (kk + hB) * 2);
            #pragma unroll
            for (int mt = 0; mt < 2; mt++)
                #pragma unroll
                for (int nt = 0; nt < 4; nt++)
                    mma16(accS[mt][nt], af[mt], &bp[nt >> 1][(nt & 1) * 2]);
        }

        // P = exp(S/8) * Zinv -> sP (half2)
        uint32_t(*sP)[ASTR] = (uint32_t(*)[ASTR])(asm_ + 128 * ASTR);
        #pragma unroll
        for (int mt = 0; mt < 2; mt++) {
            int rl = erl + mt * 16;
            #pragma unroll
            for (int nt = 0; nt < 4; nt++) {
                int cu = wC * 16 + nt * 4 + (lane & 3);
                sP[rl][cu] =
                    f2h2(__expf(accS[mt][nt][0] * 0.125f) * rz[mt][nt][0].x,
                         __expf(accS[mt][nt][1] * 0.125f) * rz[mt][nt][0].y);
                sP[rl + 8][cu] =
                    f2h2(__expf(accS[mt][nt][2] * 0.125f) * rz[mt][nt][1].x,
                         __expf(accS[mt][nt][3] * 0.125f) * rz[mt][nt][1].y);
            }
        }
        __syncthreads();  // B: sP ready

        // ---- O += P.V (128x64, contract 64) ----
        #pragma unroll
        for (int kk = 0; kk < 64; kk += 16) {
            uint32_t af[2][4], bp[2][4];
            #pragma unroll
            for (int mt = 0; mt < 2; mt++)
                ldsm4(af[mt], pB + (wR * 32 + mt * 16 + rA) * (ASTR * 4) +
                                  (kk + hA) * 2);
            #pragma unroll
            for (int p = 0; p < 2; p++)
                ldsm4(bp[p], vB + (wC * 32 + p * 16 + rB) * (ASTR * 4) +
                                 (kk + hB) * 2);
            #pragma unroll
            for (int mt = 0; mt < 2; mt++)
                #pragma unroll
                for (int nt = 0; nt < 4; nt++)
                    mma16(accO[mt][nt], af[mt], &bp[nt >> 1][(nt & 1) * 2]);
        }

        // Stage chunk c+2 (buffer last read in PV(c-1), two barriers ago).
        if (c + 2 < NN / 64) {
            uint32_t kBuf = kB0 + ((c + 2) % 3) * (64 * ASTR * 4);
            uint32_t vBuf = vB0 + ((c + 2) % 3) * (64 * ASTR * 4);
            int mb = m0 + 128;
            #pragma unroll
            for (int s = 0; s < 2; s++) {
                int seg = kseg + s * 4;
                cpa16(kBuf + (krow * ASTR + seg * 4) * 4,
                      Kh + (size_t)(mb + krow) * DD + seg * 8);
                cpa16(vBuf + (krow * ASTR + seg * 4) * 4,
                      Vth + (size_t)krow * NN + mb + seg * 8);
            }
            CP_COMMIT;
        }
    }

    #pragma unroll
    for (int mt = 0; mt < 2; mt++) {
        int r = n0 + wR * 32 + mt * 16 + (lane >> 2);
        #pragma unroll
        for (int nt = 0; nt < 4; nt++) {
            int cc = h * DKK + wC * 32 + nt * 8 + (lane & 3) * 2;
            *(float2*)&g_A[((size_t)b * NN + r) * DD + cc] =
                make_float2(accO[mt][nt][0], accO[mt][nt][1]);
            *(float2*)&g_A[((size_t)b * NN + r + 8) * DD + cc] =
                make_float2(accO[mt][nt][2], accO[mt][nt][3]);
        }
    }
}

extern "C" void kernel_launch(void* const* d_in, const int* in_sizes, int n_in,
                              void* d_out, int out_size) {
    const float* Q = (const float*)d_in[0];
    const float* K = (const float*)d_in[1];
    const float* V = (const float*)d_in[2];
    const float* Wq = (const float*)d_in[3];
    const float* bq = (const float*)d_in[4];
    const float* Wo = (const float*)d_in[5];
    const float* bo = (const float*)d_in[6];
    float* out = (float*)d_out;

    void* pA = nullptr;
    cudaGetSymbolAddress(&pA, g_A);

    cudaFuncSetAttribute(zinv_kernel, cudaFuncAttributeMaxDynamicSharedMemorySize,
                         ZINV_SMEM_BYTES);
    cudaFuncSetAttribute(attn_kernel, cudaFuncAttributeMaxDynamicSharedMemorySize,
                         ATTN_SMEM_BYTES);

    // Fork-join: V-projection runs concurrently with zinv (which only needs
    // Q/K projections). Stream/event created+destroyed per call (no device
    // memory involved); fork via event recorded on the main stream, join
    // before attn. Capturable multi-stream pattern.
    cudaStream_t s2;
    cudaStreamCreateWithFlags(&s2, cudaStreamNonBlocking);
    cudaEvent_t eFork, eJoin;
    cudaEventCreateWithFlags(&eFork, cudaEventDisableTiming);
    cudaEventCreateWithFlags(&eJoin, cudaEventDisableTiming);

    // QK projections (z = 0,1) on the main stream.
    gemm512_kernel<<<dim3(DD / 128, (BB * NN) / 128, 2), 256>>>(
        Q, K, V, Wq, bq, nullptr, 0, 0);
    cudaEventRecord(eFork, 0);
    cudaStreamWaitEvent(s2, eFork, 0);
    // V projection (z = 2) on the side stream, concurrent with zinv.
    gemm512_kernel<<<dim3(DD / 128, (BB * NN) / 128, 1), 256, 0, s2>>>(
        Q, K, V, Wq, bq, nullptr, 0, 2);

    zinv_kernel<<<dim3(NN / 128, NN / 128, BB), 512, ZINV_SMEM_BYTES>>>();

    cudaEventRecord(eJoin, s2);
    cudaStreamWaitEvent(0, eJoin, 0);

    attn_kernel<<<dim3(HH, NN / 128, BB), 256, ATTN_SMEM_BYTES>>>();
    gemm512_kernel<<<dim3(DD / 128, (BB * NN) / 128, 1), 256>>>(
        (const float*)pA, nullptr, nullptr, Wo, bo, out, 1, 0);

    cudaEventDestroy(eFork);
    cudaEventDestroy(eJoin);
    cudaStreamDestroy(s2);
}

// round 17
// speedup vs baseline: 1.2642x; 1.0381x over previous
#include <cuda_runtime.h>
#include <cuda_fp16.h>
#include <stdint.h>

#define BB 4
#define NN 2048
#define DD 512
#define HH 8
#define DKK 64

// fp16 scratch written by the projection kernel.
__device__ __align__(16) __half g_hQp[BB * NN * DD];   // [b][n][e]
__device__ __align__(16) __half g_hKp[BB * NN * DD];   // [b][n][e]
__device__ __align__(16) __half g_hVt[BB * DD * NN];   // [b][e][n]  (transposed)
__device__ __align__(16) __half g_Zh[(size_t)BB * NN * NN];  // 33.5 MB fp16 Zinv
__device__ float g_A[BB * NN * DD];

__device__ __forceinline__ uint32_t f2h2(float lo, float hi) {
    uint32_t r;
    asm("cvt.rn.f16x2.f32 %0, %1, %2;" : "=r"(r) : "f"(hi), "f"(lo));
    return r;
}
__device__ __forceinline__ uint2 f4toh(float4 v) {
    return make_uint2(f2h2(v.x, v.y), f2h2(v.z, v.w));
}
__device__ __forceinline__ void mma16(float c[4], const uint32_t a[4],
                                      const uint32_t b[2]) {
    asm volatile(
        "mma.sync.aligned.m16n8k16.row.col.f32.f16.f16.f32 "
        "{%0,%1,%2,%3},{%4,%5,%6,%7},{%8,%9},{%0,%1,%2,%3};"
        : "+f"(c[0]), "+f"(c[1]), "+f"(c[2]), "+f"(c[3])
        : "r"(a[0]), "r"(a[1]), "r"(a[2]), "r"(a[3]), "r"(b[0]), "r"(b[1]));
}
__device__ __forceinline__ void ldsm4(uint32_t r[4], uint32_t a) {
    asm volatile(
        "ldmatrix.sync.aligned.m8n8.x4.shared.b16 {%0,%1,%2,%3}, [%4];"
        : "=r"(r[0]), "=r"(r[1]), "=r"(r[2]), "=r"(r[3])
        : "r"(a));
}
__device__ __forceinline__ uint32_t smem_u32(const void* p) {
    return (uint32_t)__cvta_generic_to_shared(p);
}
__device__ __forceinline__ void cpa16(uint32_t dst, const void* src) {
    asm volatile("cp.async.ca.shared.global [%0], [%1], 16;" ::"r"(dst),
                 "l"(src));
}
#define CP_COMMIT asm volatile("cp.async.commit_group;" ::: "memory")
#define CP_WAIT1 asm volatile("cp.async.wait_group 1;" ::: "memory")
#define CP_WAIT0 asm volatile("cp.async.wait_group 0;" ::: "memory")

#define LANE_RA(lane) ((((lane) >> 3) & 1) * 8 + ((lane)&7))
#define LANE_HA(lane) (((lane) >> 4) * 8)
#define LANE_RB(lane) ((((lane) >> 4)) * 8 + ((lane)&7))
#define LANE_HB(lane) ((((lane) >> 3) & 1) * 8)

// ---------------------------------------------------------------------------
// 512-K GEMM (fp16 mma): Y[row,e] = sum_d X[row,d]*W[e,d] + bias[e]
// z = blockIdx.z + zbase: 0 -> g_hQp, 1 -> g_hKp, 2 -> g_hVt (transposed).
// mode 1: fp32 out to Yf.
// ---------------------------------------------------------------------------
#define GSTR 20

__global__ __launch_bounds__(256, 2) void gemm512_kernel(
    const float* __restrict__ X0, const float* __restrict__ X1,
    const float* __restrict__ X2, const float* __restrict__ W,
    const float* __restrict__ bias, float* __restrict__ Yf, int mode,
    int zbase) {
    const int z = blockIdx.z + zbase;
    const float* X = (z == 0) ? X0 : (z == 1) ? X1 : X2;

    __shared__ uint32_t sA[128][GSTR];
    __shared__ uint32_t sB[128][GSTR];

    const int tid = threadIdx.x;
    const int lane = tid & 31;
    const int warp = tid >> 5;
    const int wR = warp >> 2;
    const int wC = warp & 3;
    const int row0 = blockIdx.y * 128;
    const int e0 = blockIdx.x * 128;

    const int lr = tid >> 3;
    const int lcf = (tid & 7) * 4;
    const int lcu = (tid & 7) * 2;

    const uint32_t aB = smem_u32(&sA[0][0]);
    const uint32_t bB = smem_u32(&sB[0][0]);
    const int rA = LANE_RA(lane), hA = LANE_HA(lane);
    const int rB = LANE_RB(lane), hB = LANE_HB(lane);

    float acc[4][4][4] = {};
    float4 ra[4], rb[4];

    #pragma unroll
    for (int it = 0; it < 4; it++) {
        int r = lr + it * 32;
        ra[it] = *(const float4*)&X[(size_t)(row0 + r) * DD + lcf];
        rb[it] = *(const float4*)&W[(size_t)(e0 + r) * DD + lcf];
    }

    for (int k0 = 0; k0 < DD; k0 += 32) {
        #pragma unroll
        for (int it = 0; it < 4; it++) {
            int r = lr + it * 32;
            *(uint2*)&sA[r][lcu] = f4toh(ra[it]);
            *(uint2*)&sB[r][lcu] = f4toh(rb[it]);
        }
        __syncthreads();
        if (k0 + 32 < DD) {
            #pragma unroll
            for (int it = 0; it < 4; it++) {
                int r = lr + it * 32;
                ra[it] = *(const float4*)&X[(size_t)(row0 + r) * DD + k0 + 32 + lcf];
                rb[it] = *(const float4*)&W[(size_t)(e0 + r) * DD + k0 + 32 + lcf];
            }
        }
        #pragma unroll
        for (int kk = 0; kk < 32; kk += 16) {
            uint32_t af[4][4], bp[2][4];
            #pragma unroll
            for (int mt = 0; mt < 4; mt++)
                ldsm4(af[mt], aB + (wR * 64 + mt * 16 + rA) * (GSTR * 4) +
                                  (kk + hA) * 2);
            #pragma unroll
            for (int p = 0; p < 2; p++)
                ldsm4(bp[p], bB + (wC * 32 + p * 16 + rB) * (GSTR * 4) +
                                 (kk + hB) * 2);
            #pragma unroll
            for (int mt = 0; mt < 4; mt++)
                #pragma unroll
                for (int nt = 0; nt < 4; nt++)
                    mma16(acc[mt][nt], af[mt], &bp[nt >> 1][(nt & 1) * 2]);
        }
        __syncthreads();
    }

    #pragma unroll
    for (int mt = 0; mt < 4; mt++) {
        int r = row0 + wR * 64 + mt * 16 + (lane >> 2);
        #pragma unroll
        for (int nt = 0; nt < 4; nt++) {
            int c = e0 + wC * 32 + nt * 8 + (lane & 3) * 2;
            float b0 = bias[c], b1 = bias[c + 1];
            float v00 = acc[mt][nt][0] + b0, v01 = acc[mt][nt][1] + b1;
            float v10 = acc[mt][nt][2] + b0, v11 = acc[mt][nt][3] + b1;
            if (mode == 1) {
                *(float2*)&Yf[(size_t)r * DD + c] = make_float2(v00, v01);
                *(float2*)&Yf[(size_t)(r + 8) * DD + c] = make_float2(v10, v11);
            } else if (z < 2) {
                __half* Yh = z ? g_hKp : g_hQp;
                *(uint32_t*)&Yh[(size_t)r * DD + c] = f2h2(v00, v01);
                *(uint32_t*)&Yh[(size_t)(r + 8) * DD + c] = f2h2(v10, v11);
            } else {
                int bb = r >> 11, n = r & (NN - 1);
                size_t base = (size_t)bb * DD * NN;
                g_hVt[base + (size_t)c * NN + n] = __float2half_rn(v00);
                g_hVt[base + (size_t)(c + 1) * NN + n] = __float2half_rn(v01);
                g_hVt[base + (size_t)c * NN + n + 8] = __float2half_rn(v10);
                g_hVt[base + (size_t)(c + 1) * NN + n + 8] = __float2half_rn(v11);
            }
        }
    }
}

// ---------------------------------------------------------------------------
// Zinv: g_Zh[b,n,m] = fp16( 1 / sum_h exp( (q_h(n).k_h(m)) / 8 ) )
// Tile 128x128, 512 threads, 16 warps 32x32, cp.async 3-deep, 1 barrier/chunk.
// ---------------------------------------------------------------------------
#define ZBUF (2 * 128 * GSTR)
#define ZINV_SMEM_BYTES (3 * ZBUF * 4)

__global__ __launch_bounds__(512) void zinv_kernel() {
    extern __shared__ uint32_t zsm[];

    const int tid = threadIdx.x;
    const int lane = tid & 31;
    const int warp = tid >> 5;
    const int wR = warp >> 2;
    const int wC = warp & 3;
    const int b = blockIdx.z;
    const int n0 = blockIdx.y * 128;
    const int m0 = blockIdx.x * 128;
    const __half* Qh = g_hQp + (size_t)b * NN * DD;
    const __half* Kh = g_hKp + (size_t)b * NN * DD;

    const uint32_t base0 = smem_u32(zsm);
    const int rA = LANE_RA(lane), hA = LANE_HA(lane);
    const int rB = LANE_RB(lane), hB = LANE_HB(lane);

    const int crow = tid >> 2;
    const int cseg = tid & 3;

    float z[2][4][4] = {};
    float dot[2][4][4] = {};

    #pragma unroll
    for (int pc = 0; pc < 2; pc++) {
        uint32_t bufB = base0 + pc * (ZBUF * 4);
        cpa16(bufB + (crow * GSTR + cseg * 4) * 4,
              Qh + (size_t)(n0 + crow) * DD + pc * 32 + cseg * 8);
        cpa16(bufB + ((128 + crow) * GSTR + cseg * 4) * 4,
              Kh + (size_t)(m0 + crow) * DD + pc * 32 + cseg * 8);
        CP_COMMIT;
    }

    for (int ch = 0; ch < 16; ch++) {
        if (ch == 15) { CP_WAIT0; } else { CP_WAIT1; }
        __syncthreads();

        const uint32_t qB = base0 + (ch % 3) * (ZBUF * 4);
        const uint32_t kB = qB + 128 * GSTR * 4;

        #pragma unroll
        for (int kk = 0; kk < 32; kk += 16) {
            uint32_t af[2][4], bp[2][4];
            #pragma unroll
            for (int mt = 0; mt < 2; mt++)
                ldsm4(af[mt], qB + (wR * 32 + mt * 16 + rA) * (GSTR * 4) +
                                  (kk + hA) * 2);
            #pragma unroll
            for (int p = 0; p < 2; p++)
                ldsm4(bp[p], kB + (wC * 32 + p * 16 + rB) * (GSTR * 4) +
                                 (kk + hB) * 2);
            #pragma unroll
            for (int mt = 0; mt < 2; mt++)
                #pragma unroll
                for (int nt = 0; nt < 4; nt++)
                    mma16(dot[mt][nt], af[mt], &bp[nt >> 1][(nt & 1) * 2]);
        }

        if (ch & 1) {  // head boundary: fold exp
            #pragma unroll
            for (int mt = 0; mt < 2; mt++)
                #pragma unroll
                for (int nt = 0; nt < 4; nt++)
                    #pragma unroll
                    for (int i = 0; i < 4; i++) {
                        z[mt][nt][i] += __expf(dot[mt][nt][i] * 0.125f);
                        dot[mt][nt][i] = 0.0f;
                    }
        }

        if (ch + 2 < 16) {
            uint32_t bufB = base0 + ((ch + 2) % 3) * (ZBUF * 4);
            int kb = (ch + 2) * 32;
            cpa16(bufB + (crow * GSTR + cseg * 4) * 4,
                  Qh + (size_t)(n0 + crow) * DD + kb + cseg * 8);
            cpa16(bufB + ((128 + crow) * GSTR + cseg * 4) * 4,
                  Kh + (size_t)(m0 + crow) * DD + kb + cseg * 8);
            CP_COMMIT;
        }
    }

    #pragma unroll
    for (int mt = 0; mt < 2; mt++) {
        int r = n0 + wR * 32 + mt * 16 + (lane >> 2);
        #pragma unroll
        for (int nt = 0; nt < 4; nt++) {
            int c = m0 + wC * 32 + nt * 8 + (lane & 3) * 2;
            *(uint32_t*)&g_Zh[((size_t)b * NN + r) * NN + c] =
                f2h2(1.0f / z[mt][nt][0], 1.0f / z[mt][nt][1]);
            *(uint32_t*)&g_Zh[((size_t)b * NN + r + 8) * NN + c] =
                f2h2(1.0f / z[mt][nt][2], 1.0f / z[mt][nt][3]);
        }
    }
}

// ---------------------------------------------------------------------------
// attn (R16 schedule + Q fragments in REGISTERS + fp16 Zinv).
// Per block (b=z, h=x fastest, n-tile=y of 128). 256 threads, 8 warps 4x2.
// Q ldsm'd ONCE into qf[2][4][4]; S phase issues only K ldsm.
// ---------------------------------------------------------------------------
#define ASTR 36
#define ATTN_SMEM_BYTES (640 * ASTR * 4)

__global__ __launch_bounds__(256, 2) void attn_kernel() {
    extern __shared__ uint32_t asm_[];

    const int tid = threadIdx.x;
    const int lane = tid & 31;
    const int warp = tid >> 5;
    const int wR = warp >> 1;  // 0..3
    const int wC = warp & 1;   // 0..1
    const int b = blockIdx.z;
    const int h = blockIdx.x;  // h fastest
    const int n0 = blockIdx.y * 128;

    const __half* Qh = g_hQp + (size_t)b * NN * DD + h * DKK;
    const __half* Kh = g_hKp + (size_t)b * NN * DD + h * DKK;
    const __half* Vth = g_hVt + ((size_t)b * DD + h * DKK) * NN;
    const __half* Zb = g_Zh + (size_t)b * NN * NN;

    const uint32_t smB = smem_u32(asm_);
    const uint32_t qB = smB;
    const uint32_t pB = smB + 128 * ASTR * 4;
    const uint32_t kB0 = smB + 256 * ASTR * 4;
    const uint32_t vB0 = smB + 448 * ASTR * 4;
    const int rA = LANE_RA(lane), hA = LANE_HA(lane);
    const int rB = LANE_RB(lane), hB = LANE_HB(lane);

    // Q prologue: cp.async (group 0).
    {
        int qrow = tid >> 1;
        int sbase = (tid & 1) * 4;
        #pragma unroll
        for (int s = 0; s < 4; s++) {
            int seg = sbase + s;
            cpa16(qB + (qrow * ASTR + seg * 4) * 4,
                  Qh + (size_t)(n0 + qrow) * DD + seg * 8);
        }
        CP_COMMIT;
    }

    const int krow = tid >> 2;
    const int kseg = tid & 3;

    // Prologue: chunks 0,1 (groups 1,2).
    #pragma unroll
    for (int pc = 0; pc < 2; pc++) {
        uint32_t kBuf = kB0 + pc * (64 * ASTR * 4);
        uint32_t vBuf = vB0 + pc * (64 * ASTR * 4);
        #pragma unroll
        for (int s = 0; s < 2; s++) {
            int seg = kseg + s * 4;
            cpa16(kBuf + (krow * ASTR + seg * 4) * 4,
                  Kh + (size_t)(pc * 64 + krow) * DD + seg * 8);
            cpa16(vBuf + (krow * ASTR + seg * 4) * 4,
                  Vth + (size_t)krow * NN + pc * 64 + seg * 8);
        }
        CP_COMMIT;
    }

    // Wait for Q + chunk0; hoist Q fragments into registers (once).
    CP_WAIT1;
    __syncthreads();
    uint32_t qf[2][4][4];
    #pragma unroll
    for (int mt = 0; mt < 2; mt++)
        #pragma unroll
        for (int ks = 0; ks < 4; ks++)
            ldsm4(qf[mt][ks], qB + (wR * 32 + mt * 16 + rA) * (ASTR * 4) +
                                  (ks * 16 + hA) * 2);

    const int erl = wR * 32 + (lane >> 2);
    const int ecl = wC * 32 + (lane & 3) * 2;

    float accO[2][4][4] = {};

    for (int c = 0; c < NN / 64; c++) {
        const int m0 = c * 64;

        // Zinv(c) register prefetch (fp16 pairs) — hidden behind the S phase.
        uint32_t rz[2][4][2];
        #pragma unroll
        for (int mt = 0; mt < 2; mt++)
            #pragma unroll
            for (int nt = 0; nt < 4; nt++) {
                int rl = erl + mt * 16, cl = ecl + nt * 8;
                rz[mt][nt][0] =
                    *(const uint32_t*)&Zb[(size_t)(n0 + rl) * NN + m0 + cl];
                rz[mt][nt][1] =
                    *(const uint32_t*)&Zb[(size_t)(n0 + rl + 8) * NN + m0 + cl];
            }

        if (c == NN / 64 - 1) { CP_WAIT0; } else { CP_WAIT1; }
        __syncthreads();  // A: K/V(c) ready; PV(c-1) sP reads done

        const uint32_t kB = kB0 + (c % 3) * (64 * ASTR * 4);
        const uint32_t vB = vB0 + (c % 3) * (64 * ASTR * 4);

        // ---- S = Q.K^T (128x64, contract 64): af from registers ----
        float accS[2][4][4] = {};
        #pragma unroll
        for (int ks = 0; ks < 4; ks++) {
            uint32_t bp[2][4];
            #pragma unroll
            for (int p = 0; p < 2; p++)
                ldsm4(bp[p], kB + (wC * 32 + p * 16 + rB) * (ASTR * 4) +
                                 (ks * 16 + hB) * 2);
            #pragma unroll
            for (int mt = 0; mt < 2; mt++)
                #pragma unroll
                for (int nt = 0; nt < 4; nt++)
                    mma16(accS[mt][nt], qf[mt][ks], &bp[nt >> 1][(nt & 1) * 2]);
        }

        // P = exp(S/8) * Zinv(fp16) -> sP (half2)
        uint32_t(*sP)[ASTR] = (uint32_t(*)[ASTR])(asm_ + 128 * ASTR);
        #pragma unroll
        for (int mt = 0; mt < 2; mt++) {
            int rl = erl + mt * 16;
            #pragma unroll
            for (int nt = 0; nt < 4; nt++) {
                int cu = wC * 16 + nt * 4 + (lane & 3);
                float2 z0 = __half22float2(*(__half2*)&rz[mt][nt][0]);
                float2 z1 = __half22float2(*(__half2*)&rz[mt][nt][1]);
                sP[rl][cu] =
                    f2h2(__expf(accS[mt][nt][0] * 0.125f) * z0.x,
                         __expf(accS[mt][nt][1] * 0.125f) * z0.y);
                sP[rl + 8][cu] =
                    f2h2(__expf(accS[mt][nt][2] * 0.125f) * z1.x,
                         __expf(accS[mt][nt][3] * 0.125f) * z1.y);
            }
        }
        __syncthreads();  // B: sP ready

        // ---- O += P.V (128x64, contract 64) ----
        #pragma unroll
        for (int kk = 0; kk < 64; kk += 16) {
            uint32_t af[2][4], bp[2][4];
            #pragma unroll
            for (int mt = 0; mt < 2; mt++)
                ldsm4(af[mt], pB + (wR * 32 + mt * 16 + rA) * (ASTR * 4) +
                                  (kk + hA) * 2);
            #pragma unroll
            for (int p = 0; p < 2; p++)
                ldsm4(bp[p], vB + (wC * 32 + p * 16 + rB) * (ASTR * 4) +
                                 (kk + hB) * 2);
            #pragma unroll
            for (int mt = 0; mt < 2; mt++)
                #pragma unroll
                for (int nt = 0; nt < 4; nt++)
                    mma16(accO[mt][nt], af[mt], &bp[nt >> 1][(nt & 1) * 2]);
        }

        // Stage chunk c+2 (buffer last read in PV(c-1), two barriers ago).
        if (c + 2 < NN / 64) {
            uint32_t kBuf = kB0 + ((c + 2) % 3) * (64 * ASTR * 4);
            uint32_t vBuf = vB0 + ((c + 2) % 3) * (64 * ASTR * 4);
            int mb = m0 + 128;
            #pragma unroll
            for (int s = 0; s < 2; s++) {
                int seg = kseg + s * 4;
                cpa16(kBuf + (krow * ASTR + seg * 4) * 4,
                      Kh + (size_t)(mb + krow) * DD + seg * 8);
                cpa16(vBuf + (krow * ASTR + seg * 4) * 4,
                      Vth + (size_t)krow * NN + mb + seg * 8);
            }
            CP_COMMIT;
        }
    }

    #pragma unroll
    for (int mt = 0; mt < 2; mt++) {
        int r = n0 + wR * 32 + mt * 16 + (lane >> 2);
        #pragma unroll
        for (int nt = 0; nt < 4; nt++) {
            int cc = h * DKK + wC * 32 + nt * 8 + (lane & 3) * 2;
            *(float2*)&g_A[((size_t)b * NN + r) * DD + cc] =
                make_float2(accO[mt][nt][0], accO[mt][nt][1]);
            *(float2*)&g_A[((size_t)b * NN + r + 8) * DD + cc] =
                make_float2(accO[mt][nt][2], accO[mt][nt][3]);
        }
    }
}

extern "C" void kernel_launch(void* const* d_in, const int* in_sizes, int n_in,
                              void* d_out, int out_size) {
    const float* Q = (const float*)d_in[0];
    const float* K = (const float*)d_in[1];
    const float* V = (const float*)d_in[2];
    const float* Wq = (const float*)d_in[3];
    const float* bq = (const float*)d_in[4];
    const float* Wo = (const float*)d_in[5];
    const float* bo = (const float*)d_in[6];
    float* out = (float*)d_out;

    void* pA = nullptr;
    cudaGetSymbolAddress(&pA, g_A);

    cudaFuncSetAttribute(zinv_kernel, cudaFuncAttributeMaxDynamicSharedMemorySize,
                         ZINV_SMEM_BYTES);
    cudaFuncSetAttribute(attn_kernel, cudaFuncAttributeMaxDynamicSharedMemorySize,
                         ATTN_SMEM_BYTES);

    // Fork-join: V-projection runs concurrently with zinv.
    cudaStream_t s2;
    cudaStreamCreateWithFlags(&s2, cudaStreamNonBlocking);
    cudaEvent_t eFork, eJoin;
    cudaEventCreateWithFlags(&eFork, cudaEventDisableTiming);
    cudaEventCreateWithFlags(&eJoin, cudaEventDisableTiming);

    gemm512_kernel<<<dim3(DD / 128, (BB * NN) / 128, 2), 256>>>(
        Q, K, V, Wq, bq, nullptr, 0, 0);
    cudaEventRecord(eFork, 0);
    cudaStreamWaitEvent(s2, eFork, 0);
    gemm512_kernel<<<dim3(DD / 128, (BB * NN) / 128, 1), 256, 0, s2>>>(
        Q, K, V, Wq, bq, nullptr, 0, 2);

    zinv_kernel<<<dim3(NN / 128, NN / 128, BB), 512, ZINV_SMEM_BYTES>>>();

    cudaEventRecord(eJoin, s2);
    cudaStreamWaitEvent(0, eJoin, 0);

    attn_kernel<<<dim3(HH, NN / 128, BB), 256, ATTN_SMEM_BYTES>>>();
    gemm512_kernel<<<dim3(DD / 128, (BB * NN) / 128, 1), 256>>>(
        (const float*)pA, nullptr, nullptr, Wo, bo, out, 1, 0);

    cudaEventDestroy(eFork);
    cudaEventDestroy(eJoin);
    cudaStreamDestroy(s2);
}